// round 15
// baseline (speedup 1.0000x reference)
#include <cuda_runtime.h>
#include <cuda_bf16.h>
#include <cstdint>

#define NTH 256

// ============================ helpers ============================

__device__ __forceinline__ void cp16(void* smem_dst, const void* gsrc, bool pred) {
    uint32_t sa = (uint32_t)__cvta_generic_to_shared(smem_dst);
    int sz = pred ? 16 : 0;
    asm volatile("cp.async.ca.shared.global [%0], [%1], 16, %2;"
                 :: "r"(sa), "l"(gsrc), "r"(sz));
}
__device__ __forceinline__ void cp_commit() { asm volatile("cp.async.commit_group;"); }
template<int N> __device__ __forceinline__ void cp_waitN() {
    asm volatile("cp.async.wait_group %0;" :: "n"(N));
}

__device__ __forceinline__ void ldmx4(uint32_t r[4], uint32_t addr) {
    asm volatile("ldmatrix.sync.aligned.m8n8.x4.shared.b16 {%0,%1,%2,%3}, [%4];"
                 : "=r"(r[0]), "=r"(r[1]), "=r"(r[2]), "=r"(r[3]) : "r"(addr));
}

__device__ __forceinline__ void mma16816(float c[4], const uint32_t a[4],
                                         uint32_t b0, uint32_t b1) {
    asm volatile(
        "mma.sync.aligned.m16n8k16.row.col.f32.bf16.bf16.f32 "
        "{%0,%1,%2,%3}, {%4,%5,%6,%7}, {%8,%9}, {%0,%1,%2,%3};"
        : "+f"(c[0]), "+f"(c[1]), "+f"(c[2]), "+f"(c[3])
        : "r"(a[0]), "r"(a[1]), "r"(a[2]), "r"(a[3]), "r"(b0), "r"(b1));
}

__device__ __forceinline__ float eluf(float v) {
    return v > 0.f ? v : expm1f(v);
}

// ============================ prep kernels ============================

// x [16][64][4096] fp32 -> act0 [16][4096][64] bf16 hi/lo (tiled transpose)
__global__ void prep_acts(const float* __restrict__ x,
                          __nv_bfloat16* __restrict__ h,
                          __nv_bfloat16* __restrict__ l) {
    __shared__ float tile[32][33];
    int tx = threadIdx.x & 31, ty = threadIdx.x >> 5;  // 32x8
    int t0 = blockIdx.x * 32, c0 = blockIdx.y * 32, b = blockIdx.z;
    #pragma unroll
    for (int k = 0; k < 4; ++k)
        tile[ty + 8 * k][tx] = x[((size_t)(b * 64 + c0 + ty + 8 * k)) * 4096 + t0 + tx];
    __syncthreads();
    #pragma unroll
    for (int k = 0; k < 4; ++k) {
        float v = tile[tx][ty + 8 * k];
        size_t o = ((size_t)(b * 4096 + t0 + ty + 8 * k)) * 64 + c0 + tx;
        __nv_bfloat16 hh = __float2bfloat16(v);
        h[o] = hh;
        l[o] = __float2bfloat16(v - __bfloat162float(hh));
    }
}

// Weight operands: per conv [co][Ktot] bf16.
// K2 slices s: {hi t0, hi t1, lo t0, lo t1, hi t0, hi t1}; K1: {hi, hi, lo}
#define WP_DS    0u
#define WP_C10   24576u
#define WP_C20   73728u
#define WP_L(s)  (73728u + (unsigned)(s) * 98304u)
#define WP_TOTAL 958464u

__global__ void prep_weights(const float* __restrict__ ds_w,
                             const float* __restrict__ w1_0,
                             const float* __restrict__ w2_0,
                             const float* __restrict__ W1,
                             const float* __restrict__ W2,
                             __nv_bfloat16* __restrict__ dst) {
    const unsigned LWf = 128u * 128u * 2u;
    for (unsigned id = blockIdx.x * blockDim.x + threadIdx.x; id < WP_TOTAL;
         id += gridDim.x * blockDim.x) {
        float w;
        unsigned s;
        bool isK1 = false;
        if (id < WP_C10) {                    // ds: CIN=64 K=1, Ktot=192
            unsigned local = id;
            unsigned co = local / 192, rem = local % 192;
            s = rem / 64;
            unsigned ci = rem % 64;
            w = ds_w[co * 64 + ci];
            isK1 = true;
        } else if (id < WP_C20) {             // c1_0: CIN=64 K=2, Ktot=384
            unsigned local = id - WP_C10;
            unsigned co = local / 384, rem = local % 384;
            s = rem / 64;
            unsigned ci = rem % 64, tap = s & 1;
            w = w1_0[(co * 64 + ci) * 2 + tap];
        } else {                              // CIN=128 K=2, Ktot=768
            unsigned local = id - WP_C20;
            unsigned seg = local / 98304u;    // 0..8
            unsigned rem = local % 98304u;
            unsigned co = rem / 768, r = rem % 768;
            s = r / 128;
            unsigned ci = r % 128, tap = s & 1;
            const float* src = (seg == 0) ? w2_0
                             : ((seg & 1) ? (W1 + ((seg - 1) / 2) * LWf)
                                          : (W2 + (seg / 2 - 1) * LWf));
            w = src[(co * 128 + ci) * 2 + tap];
        }
        bool lo = isK1 ? (s == 2) : (s >= 2 && s < 4);
        __nv_bfloat16 hh = __float2bfloat16(w);
        __nv_bfloat16 v = lo ? __float2bfloat16(w - __bfloat162float(hh)) : hh;
        dst[id] = v;
    }
}

// ============================ conv kernel (mma.sync bf16) ============================
// D[co=128, t=128] per CTA, 256 threads (8 warps, 2m x 4n; warp = 64co x 32t),
// 2 CTAs/SM. 4 distinct A slices (hi0, hi1, lo0, lo1); lifetime-scheduled staging:
//   CIN=64: everything resident, one prologue wait, zero mainloop syncs.
//   CIN=128: slice2/3 staged into dead B_lo / A0 regions, overlapped with compute.
// MODE 0: elu(conv+b) -> hi/lo bf16 [b][t][co]
// MODE 1: elu(elu(conv+b)+res) -> hi/lo
// MODE 2: final: elu(elu(conv+b)+res)+skip -> fp32 [b][co][t]
// MODE 3: conv+b -> fp32 [b][t][co] (downsample)
template<int CIN, int KSIZE, int MODE, int D, bool RESF32>
__global__ void __launch_bounds__(NTH, 2)
conv_tc(const __nv_bfloat16* __restrict__ in_hi,
        const __nv_bfloat16* __restrict__ in_lo,
        const __nv_bfloat16* __restrict__ wp,      // [128][Ktot] bf16
        const float* __restrict__ bias,
        const void* __restrict__ res_h,            // float* if RESF32 else bf16*
        const __nv_bfloat16* __restrict__ res_l,
        const __nv_bfloat16* __restrict__ skip_h,
        const __nv_bfloat16* __restrict__ skip_l,
        void* __restrict__ out_h,                  // bf16* or float* per MODE
        __nv_bfloat16* __restrict__ out_l)
{
    constexpr int TTI   = 128;                       // t-tile
    constexpr int KTOT  = 3 * KSIZE * CIN;           // wp row stride
    constexpr int PAD   = (CIN == 128) ? 136 : 72;   // bf16 row stride
    constexpr int RB    = PAD * 2;                   // row bytes
    constexpr int BROWS = TTI + D;
    constexpr int BT    = BROWS * RB;
    constexpr int AT    = 128 * RB;
    constexpr int GPB   = CIN / 8;                   // 16B granules per row
    constexpr int KS    = CIN / 16;                  // k16 steps per pass

    extern __shared__ __align__(16) char smem[];
    char* smBhi = smem;
    char* smBlo = smem + BT;
    float* tr = (float*)smem;                        // reused post-compute
    __shared__ float sbias[128];

    const int tid  = threadIdx.x;
    const int lane = tid & 31;
    const int w    = tid >> 5;
    const int t0   = blockIdx.x * TTI;
    const int b    = blockIdx.y;
    const int m0w  = (w & 1) * 64;
    const int n0w  = (w >> 1) * 32;

    if (tid < 128) sbias[tid] = bias[tid];

    // ---- ldmatrix lane base offsets ----
    const uint32_t aRow  = m0w + (lane & 15);
    const uint32_t aColB = ((lane >> 4) * 8) * 2;
    const uint32_t bRow  = n0w + (lane & 7) + ((lane >> 4) << 3);
    const uint32_t bColB = (((lane >> 3) & 1) * 8) * 2;

    float acc[4][4][4];
    #pragma unroll
    for (int mt = 0; mt < 4; ++mt)
        #pragma unroll
        for (int nt = 0; nt < 4; ++nt)
            #pragma unroll
            for (int j = 0; j < 4; ++j) acc[mt][nt][j] = 0.f;

    // ---- staging helpers ----
    auto stageB = [&](char* dst, const __nv_bfloat16* src) {
        for (int i = tid; i < BROWS * GPB; i += NTH) {
            int r = i / GPB, gi = i - r * GPB;
            int t = t0 - D + r;
            cp16(dst + r * RB + gi * 16,
                 src + ((size_t)(b * 4096 + t)) * CIN + gi * 8, t >= 0);
        }
    };
    auto stageA = [&](char* dst, int slice) {
        const __nv_bfloat16* wsrc = wp + (size_t)slice * CIN;
        for (int i = tid; i < 128 * GPB; i += NTH) {
            int r = i / GPB, gi = i - r * GPB;
            cp16(dst + r * RB + gi * 16, wsrc + (size_t)r * KTOT + gi * 8, true);
        }
    };
    auto dopass = [&](char* aBuf, char* bBuf, int rAdd) {
        const uint32_t aBase = (uint32_t)__cvta_generic_to_shared(aBuf) +
                               aRow * RB + aColB;
        const uint32_t bBase = (uint32_t)__cvta_generic_to_shared(bBuf) +
                               (bRow + rAdd) * RB + bColB;
        #pragma unroll
        for (int kk = 0; kk < KS; ++kk) {
            const uint32_t ko = kk * 32;   // 16 bf16
            uint32_t a[4][4];
            #pragma unroll
            for (int mt = 0; mt < 4; ++mt)
                ldmx4(a[mt], aBase + mt * 16 * RB + ko);
            uint32_t b0[4], b1[4];
            ldmx4(b0, bBase + ko);                 // n tiles 0,1
            ldmx4(b1, bBase + 16 * RB + ko);       // n tiles 2,3
            #pragma unroll
            for (int mt = 0; mt < 4; ++mt) {
                mma16816(acc[mt][0], a[mt], b0[0], b0[1]);
                mma16816(acc[mt][1], a[mt], b0[2], b0[3]);
                mma16816(acc[mt][2], a[mt], b1[0], b1[1]);
                mma16816(acc[mt][3], a[mt], b1[2], b1[3]);
            }
        }
    };

    if constexpr (CIN == 64) {
        // ---- all-resident: 2 B tiles + all A slices, one wait, no mainloop syncs ----
        char* A0 = smem + 2 * BT;
        stageB(smBhi, in_hi);
        stageB(smBlo, in_lo);
        if (KSIZE == 2) {
            stageA(A0 + 0 * AT, 0); stageA(A0 + 1 * AT, 1);
            stageA(A0 + 2 * AT, 2); stageA(A0 + 3 * AT, 3);
        } else {
            stageA(A0 + 0 * AT, 0); stageA(A0 + 1 * AT, 2);
        }
        cp_commit();
        cp_waitN<0>(); __syncthreads();
        if (KSIZE == 2) {
            dopass(A0 + 0 * AT, smBlo, 0);   // wh0 * xl(t-D)
            dopass(A0 + 0 * AT, smBhi, 0);   // wh0 * xh(t-D)
            dopass(A0 + 1 * AT, smBlo, D);   // wh1 * xl(t)
            dopass(A0 + 1 * AT, smBhi, D);   // wh1 * xh(t)
            dopass(A0 + 2 * AT, smBhi, 0);   // wl0 * xh(t-D)
            dopass(A0 + 3 * AT, smBhi, D);   // wl1 * xh(t)
        } else {
            dopass(A0 + 0 * AT, smBlo, 0);   // wh * xl
            dopass(A0 + 0 * AT, smBhi, 0);   // wh * xh
            dopass(A0 + 1 * AT, smBhi, 0);   // wl * xh
        }
    } else {
        // ---- CIN=128: single A slot + dead-region reuse, overlapped staging ----
        char* A0 = smem + 2 * BT;
        stageB(smBhi, in_hi);
        stageB(smBlo, in_lo);
        stageA(A0, 0);
        cp_commit();                          // g0
        cp_waitN<0>(); __syncthreads();
        dopass(A0, smBlo, 0);                 // P1: wh0 * xl(t-D)
        dopass(A0, smBhi, 0);                 // P2: wh0 * xh(t-D)
        __syncthreads();                      // A0 readers done
        stageA(A0, 1); cp_commit();           // g1 (exposed)
        cp_waitN<0>(); __syncthreads();
        dopass(A0, smBlo, D);                 // P3: wh1 * xl(t)
        __syncthreads();                      // Blo readers done
        stageA(smBlo, 2); cp_commit();        // g2 -> dead Blo region (overlaps P4)
        dopass(A0, smBhi, D);                 // P4: wh1 * xh(t)
        __syncthreads();                      // A0 readers done
        stageA(A0, 3); cp_commit();           // g3 (overlaps P5)
        cp_waitN<1>(); __syncthreads();       // g2 arrived
        dopass(smBlo, smBhi, 0);              // P5: wl0 * xh(t-D)
        cp_waitN<0>(); __syncthreads();       // g3 arrived
        dopass(A0, smBhi, D);                 // P6: wl1 * xh(t)
    }

    __syncthreads();   // compute done; smem reusable

    // ---- phase A: accum -> smem [t][co] (+bias) ----
    {
        int g = lane >> 2, tig = lane & 3;
        #pragma unroll
        for (int mt = 0; mt < 4; ++mt)
            #pragma unroll
            for (int nt = 0; nt < 4; ++nt)
                #pragma unroll
                for (int j = 0; j < 4; ++j) {
                    int co = m0w + mt * 16 + g + ((j & 2) ? 8 : 0);
                    int tl = n0w + nt * 8 + tig * 2 + (j & 1);
                    tr[tl * 129 + co] = acc[mt][nt][j] + sbias[co];
                }
    }
    __syncthreads();

    // ---- phase B: epilogue, [t][co] order (coalesced) ----
    {
        int co = tid & 127;
        int r0 = tid >> 7;   // 0..1
        #pragma unroll 4
        for (int i = 0; i < 64; ++i) {
            int r = r0 + 2 * i;
            int t = t0 + r;
            size_t gidx = ((size_t)(b * 4096 + t)) * 128 + co;
            float v = tr[r * 129 + co];
            float y;
            if (MODE == 0) {
                y = eluf(v);
            } else if (MODE == 3) {
                y = v;
            } else {
                float rv;
                if (RESF32)
                    rv = ((const float*)res_h)[gidx];
                else
                    rv = __bfloat162float(((const __nv_bfloat16*)res_h)[gidx]) +
                         __bfloat162float(res_l[gidx]);
                y = eluf(eluf(v) + rv);
                if (MODE == 2)
                    y += __bfloat162float(skip_h[gidx]) +
                         __bfloat162float(skip_l[gidx]);
            }
            if (MODE == 3) {
                ((float*)out_h)[gidx] = y;
            } else if (MODE == 2) {
                tr[r * 129 + co] = y;    // own slot; transposed write next
            } else {
                __nv_bfloat16 hh = __float2bfloat16(y);
                ((__nv_bfloat16*)out_h)[gidx] = hh;
                out_l[gidx] = __float2bfloat16(y - __bfloat162float(hh));
            }
        }
    }

    if (MODE == 2) {
        __syncthreads();
        float* outp = (float*)out_h;
        for (int co = w; co < 128; co += 8) {
            #pragma unroll
            for (int m = 0; m < 4; ++m) {
                int r = lane + 32 * m;
                outp[((size_t)(b * 128 + co)) * 4096 + t0 + r] = tr[r * 129 + co];
            }
        }
    }
}

// ============================ scratch ============================

#define AE64  ((size_t)16 * 4096 * 64)
#define AE128 ((size_t)16 * 4096 * 128)
__device__ __nv_bfloat16 g_a0h[AE64], g_a0l[AE64];
__device__ __nv_bfloat16 g_Th[AE128], g_Tl[AE128];
__device__ __nv_bfloat16 g_Ah[AE128], g_Al[AE128];
__device__ __nv_bfloat16 g_Bh[AE128], g_Bl[AE128];
__device__ __nv_bfloat16 g_Ch[AE128], g_Cl[AE128];
__device__ float         g_ds[AE128];
__device__ __nv_bfloat16 g_wp[WP_TOTAL];

// host-side smem size mirror
static int smem_for(int CIN, int KS, int D) {
    int pad = (CIN == 128) ? 136 : 72;
    int rb = pad * 2;
    int BT = (128 + D) * rb, AT = 128 * rb;
    int stage;
    if (CIN == 64) stage = 2 * BT + ((KS == 2) ? 4 : 2) * AT;
    else           stage = 2 * BT + AT;
    int tr = 128 * 129 * 4;
    return stage > tr ? stage : tr;
}

// ============================ launcher ============================

extern "C" void kernel_launch(void* const* d_in, const int* in_sizes, int n_in,
                              void* d_out, int out_size) {
    const float* x    = (const float*)d_in[0];
    const float* w1_0 = (const float*)d_in[1];
    const float* b1_0 = (const float*)d_in[2];
    const float* w2_0 = (const float*)d_in[3];
    const float* b2_0 = (const float*)d_in[4];
    const float* ds_w = (const float*)d_in[5];
    const float* ds_b = (const float*)d_in[6];
    const float* W1   = (const float*)d_in[7];
    const float* B1   = (const float*)d_in[8];
    const float* W2   = (const float*)d_in[9];
    const float* B2   = (const float*)d_in[10];
    float* out = (float*)d_out;

    __nv_bfloat16 *a0h, *a0l, *Th, *Tl, *Ah, *Al, *Bh, *Bl, *Ch, *Cl, *wp;
    float *dsO;
    cudaGetSymbolAddress((void**)&a0h, g_a0h); cudaGetSymbolAddress((void**)&a0l, g_a0l);
    cudaGetSymbolAddress((void**)&Th, g_Th);   cudaGetSymbolAddress((void**)&Tl, g_Tl);
    cudaGetSymbolAddress((void**)&Ah, g_Ah);   cudaGetSymbolAddress((void**)&Al, g_Al);
    cudaGetSymbolAddress((void**)&Bh, g_Bh);   cudaGetSymbolAddress((void**)&Bl, g_Bl);
    cudaGetSymbolAddress((void**)&Ch, g_Ch);   cudaGetSymbolAddress((void**)&Cl, g_Cl);
    cudaGetSymbolAddress((void**)&dsO, g_ds);  cudaGetSymbolAddress((void**)&wp, g_wp);

    prep_weights<<<512, 256>>>(ds_w, w1_0, w2_0, W1, W2, wp);
    prep_acts<<<dim3(128, 2, 16), 256>>>(x, a0h, a0l);

    dim3 grid(32, 16);

    #define SETSM(CIN, KS, MODE, D, RF) cudaFuncSetAttribute( \
        (conv_tc<CIN, KS, MODE, D, RF>), \
        cudaFuncAttributeMaxDynamicSharedMemorySize, smem_for(CIN, KS, D))
    SETSM(64, 1, 3, 0, false);
    SETSM(64, 2, 0, 1, false);
    SETSM(128, 2, 1, 1, true);
    SETSM(128, 2, 0, 2, false);
    SETSM(128, 2, 1, 2, false);
    SETSM(128, 2, 0, 4, false);
    SETSM(128, 2, 1, 4, false);
    SETSM(128, 2, 0, 8, false);
    SETSM(128, 2, 1, 8, false);
    SETSM(128, 2, 0, 16, false);
    SETSM(128, 2, 2, 16, false);

    // layer 0
    conv_tc<64, 1, 3, 0, false><<<grid, NTH, smem_for(64, 1, 0)>>>(
        a0h, a0l, wp + WP_DS, ds_b, nullptr, nullptr, nullptr, nullptr, dsO, nullptr);
    conv_tc<64, 2, 0, 1, false><<<grid, NTH, smem_for(64, 2, 1)>>>(
        a0h, a0l, wp + WP_C10, b1_0, nullptr, nullptr, nullptr, nullptr, Th, Tl);
    conv_tc<128, 2, 1, 1, true><<<grid, NTH, smem_for(128, 2, 1)>>>(
        Th, Tl, wp + WP_C20, b2_0, dsO, nullptr, nullptr, nullptr, Ah, Al);   // A = x1
    // layer 1 (d=2)
    conv_tc<128, 2, 0, 2, false><<<grid, NTH, smem_for(128, 2, 2)>>>(
        Ah, Al, wp + WP_L(1), B1 + 0, nullptr, nullptr, nullptr, nullptr, Th, Tl);
    conv_tc<128, 2, 1, 2, false><<<grid, NTH, smem_for(128, 2, 2)>>>(
        Th, Tl, wp + WP_L(2), B2 + 0, Ah, Al, nullptr, nullptr, Bh, Bl);      // B = x2
    // layer 2 (d=4)
    conv_tc<128, 2, 0, 4, false><<<grid, NTH, smem_for(128, 2, 4)>>>(
        Bh, Bl, wp + WP_L(3), B1 + 128, nullptr, nullptr, nullptr, nullptr, Th, Tl);
    conv_tc<128, 2, 1, 4, false><<<grid, NTH, smem_for(128, 2, 4)>>>(
        Th, Tl, wp + WP_L(4), B2 + 128, Bh, Bl, nullptr, nullptr, Ch, Cl);    // C = x3
    // layer 3 (d=8)
    conv_tc<128, 2, 0, 8, false><<<grid, NTH, smem_for(128, 2, 8)>>>(
        Ch, Cl, wp + WP_L(5), B1 + 256, nullptr, nullptr, nullptr, nullptr, Th, Tl);
    conv_tc<128, 2, 1, 8, false><<<grid, NTH, smem_for(128, 2, 8)>>>(
        Th, Tl, wp + WP_L(6), B2 + 256, Ch, Cl, nullptr, nullptr, Bh, Bl);    // B = x4
    // layer 4 (d=16) + final skip (x1 = A)
    conv_tc<128, 2, 0, 16, false><<<grid, NTH, smem_for(128, 2, 16)>>>(
        Bh, Bl, wp + WP_L(7), B1 + 384, nullptr, nullptr, nullptr, nullptr, Th, Tl);
    conv_tc<128, 2, 2, 16, false><<<grid, NTH, smem_for(128, 2, 16)>>>(
        Th, Tl, wp + WP_L(8), B2 + 384, Bh, Bl, Ah, Al, out, nullptr);
}

// round 16
// speedup vs baseline: 1.2047x; 1.2047x over previous
#include <cuda_runtime.h>
#include <cuda_bf16.h>
#include <cstdint>

#define NTH 256

// ============================ helpers ============================

__device__ __forceinline__ void cp16(void* smem_dst, const void* gsrc, bool pred) {
    uint32_t sa = (uint32_t)__cvta_generic_to_shared(smem_dst);
    int sz = pred ? 16 : 0;
    asm volatile("cp.async.ca.shared.global [%0], [%1], 16, %2;"
                 :: "r"(sa), "l"(gsrc), "r"(sz));
}
__device__ __forceinline__ void cp_commit() { asm volatile("cp.async.commit_group;"); }
__device__ __forceinline__ void cp_wait0()  { asm volatile("cp.async.wait_group 0;"); }

__device__ __forceinline__ void ldmx4(uint32_t r[4], uint32_t addr) {
    asm volatile("ldmatrix.sync.aligned.m8n8.x4.shared.b16 {%0,%1,%2,%3}, [%4];"
                 : "=r"(r[0]), "=r"(r[1]), "=r"(r[2]), "=r"(r[3]) : "r"(addr));
}

__device__ __forceinline__ void mma16816(float c[4], const uint32_t a[4],
                                         uint32_t b0, uint32_t b1) {
    asm volatile(
        "mma.sync.aligned.m16n8k16.row.col.f32.bf16.bf16.f32 "
        "{%0,%1,%2,%3}, {%4,%5,%6,%7}, {%8,%9}, {%0,%1,%2,%3};"
        : "+f"(c[0]), "+f"(c[1]), "+f"(c[2]), "+f"(c[3])
        : "r"(a[0]), "r"(a[1]), "r"(a[2]), "r"(a[3]), "r"(b0), "r"(b1));
}

__device__ __forceinline__ float eluf(float v) {
    return v > 0.f ? v : expm1f(v);
}

// ============================ prep kernels ============================

// x [16][64][4096] fp32 -> act0 [16][4096][64] bf16 hi/lo (tiled transpose)
__global__ void prep_acts(const float* __restrict__ x,
                          __nv_bfloat16* __restrict__ h,
                          __nv_bfloat16* __restrict__ l) {
    __shared__ float tile[32][33];
    int tx = threadIdx.x & 31, ty = threadIdx.x >> 5;  // 32x8
    int t0 = blockIdx.x * 32, c0 = blockIdx.y * 32, b = blockIdx.z;
    #pragma unroll
    for (int k = 0; k < 4; ++k)
        tile[ty + 8 * k][tx] = x[((size_t)(b * 64 + c0 + ty + 8 * k)) * 4096 + t0 + tx];
    __syncthreads();
    #pragma unroll
    for (int k = 0; k < 4; ++k) {
        float v = tile[tx][ty + 8 * k];
        size_t o = ((size_t)(b * 4096 + t0 + ty + 8 * k)) * 64 + c0 + tx;
        __nv_bfloat16 hh = __float2bfloat16(v);
        h[o] = hh;
        l[o] = __float2bfloat16(v - __bfloat162float(hh));
    }
}

// Weight operands: per conv [co][Ktot] bf16.
// K2 slices s: {hi t0, hi t1, lo t0, lo t1, hi t0, hi t1}; K1: {hi, hi, lo}
#define WP_DS    0u
#define WP_C10   24576u
#define WP_C20   73728u
#define WP_L(s)  (73728u + (unsigned)(s) * 98304u)
#define WP_TOTAL 958464u

__global__ void prep_weights(const float* __restrict__ ds_w,
                             const float* __restrict__ w1_0,
                             const float* __restrict__ w2_0,
                             const float* __restrict__ W1,
                             const float* __restrict__ W2,
                             __nv_bfloat16* __restrict__ dst) {
    const unsigned LWf = 128u * 128u * 2u;
    for (unsigned id = blockIdx.x * blockDim.x + threadIdx.x; id < WP_TOTAL;
         id += gridDim.x * blockDim.x) {
        float w;
        unsigned s;
        bool isK1 = false;
        if (id < WP_C10) {                    // ds: CIN=64 K=1, Ktot=192
            unsigned local = id;
            unsigned co = local / 192, rem = local % 192;
            s = rem / 64;
            unsigned ci = rem % 64;
            w = ds_w[co * 64 + ci];
            isK1 = true;
        } else if (id < WP_C20) {             // c1_0: CIN=64 K=2, Ktot=384
            unsigned local = id - WP_C10;
            unsigned co = local / 384, rem = local % 384;
            s = rem / 64;
            unsigned ci = rem % 64, tap = s & 1;
            w = w1_0[(co * 64 + ci) * 2 + tap];
        } else {                              // CIN=128 K=2, Ktot=768
            unsigned local = id - WP_C20;
            unsigned seg = local / 98304u;    // 0..8
            unsigned rem = local % 98304u;
            unsigned co = rem / 768, r = rem % 768;
            s = r / 128;
            unsigned ci = r % 128, tap = s & 1;
            const float* src = (seg == 0) ? w2_0
                             : ((seg & 1) ? (W1 + ((seg - 1) / 2) * LWf)
                                          : (W2 + (seg / 2 - 1) * LWf));
            w = src[(co * 128 + ci) * 2 + tap];
        }
        bool lo = isK1 ? (s == 2) : (s >= 2 && s < 4);
        __nv_bfloat16 hh = __float2bfloat16(w);
        __nv_bfloat16 v = lo ? __float2bfloat16(w - __bfloat162float(hh)) : hh;
        dst[id] = v;
    }
}

// ============================ conv kernel (mma.sync bf16) ============================
// D[co=128, t=128] per CTA, 256 threads (8 warps, 2m x 4n; warp = 64co x 32t),
// 2 CTAs/SM. Single A buffer, sync-staged per segment (R14 schedule);
// staging stalls hidden by the co-resident CTA. Vectorized co-pair epilogue.
// MODE 0: elu(conv+b) -> hi/lo bf16 [b][t][co]
// MODE 1: elu(elu(conv+b)+res) -> hi/lo
// MODE 2: final: elu(elu(conv+b)+res)+skip -> fp32 [b][co][t]
// MODE 3: conv+b -> fp32 [b][t][co] (downsample)
template<int CIN, int KSIZE, int MODE, int D, bool RESF32>
__global__ void __launch_bounds__(NTH, 2)
conv_tc(const __nv_bfloat16* __restrict__ in_hi,
        const __nv_bfloat16* __restrict__ in_lo,
        const __nv_bfloat16* __restrict__ wp,      // [128][Ktot] bf16
        const float* __restrict__ bias,
        const void* __restrict__ res_h,            // float* if RESF32 else bf16*
        const __nv_bfloat16* __restrict__ res_l,
        const __nv_bfloat16* __restrict__ skip_h,
        const __nv_bfloat16* __restrict__ skip_l,
        void* __restrict__ out_h,                  // bf16* or float* per MODE
        __nv_bfloat16* __restrict__ out_l)
{
    constexpr int TTI   = 128;                       // t-tile
    constexpr int NSEG  = 3 * KSIZE;
    constexpr int KTOT  = NSEG * CIN;
    constexpr int PAD   = (CIN == 128) ? 136 : 72;   // bf16 row stride
    constexpr int RB    = PAD * 2;                   // row bytes
    constexpr int BROWS = TTI + D;
    constexpr int BT    = BROWS * RB;
    constexpr int GPB   = CIN / 8;                   // 16B granules per row
    constexpr int KS    = CIN / 16;                  // k16 steps per segment
    constexpr int TRS   = 130;                       // tr row stride (even -> f2 aligned)

    extern __shared__ __align__(16) char smem[];
    char* smBhi = smem;
    char* smBlo = smem + BT;
    char* smA   = smem + 2 * BT;                     // single buffer
    float* tr = (float*)smem;                        // reused post-compute

    const int tid  = threadIdx.x;
    const int lane = tid & 31;
    const int w    = tid >> 5;
    const int t0   = blockIdx.x * TTI;
    const int b    = blockIdx.y;
    const int m0w  = (w & 1) * 64;
    const int n0w  = (w >> 1) * 32;

    // ---- stage B (hi and lo), rows t0-D .. t0+TTI-1 ----
    for (int i = tid; i < BROWS * GPB; i += NTH) {
        int r = i / GPB, gi = i - r * GPB;
        int t = t0 - D + r;
        const size_t gofs = ((size_t)(b * 4096 + t)) * CIN + gi * 8;
        cp16(smBhi + r * RB + gi * 16, in_hi + gofs, t >= 0);
        cp16(smBlo + r * RB + gi * 16, in_lo + gofs, t >= 0);
    }
    cp_commit();

    // ---- ldmatrix lane base offsets ----
    const uint32_t aRow  = m0w + (lane & 15);
    const uint32_t aColB = ((lane >> 4) * 8) * 2;
    const uint32_t bRow  = n0w + (lane & 7) + ((lane >> 4) << 3);
    const uint32_t bColB = (((lane >> 3) & 1) * 8) * 2;

    float acc[4][4][4];
    #pragma unroll
    for (int mt = 0; mt < 4; ++mt)
        #pragma unroll
        for (int nt = 0; nt < 4; ++nt)
            #pragma unroll
            for (int j = 0; j < 4; ++j) acc[mt][nt][j] = 0.f;

    #pragma unroll 1
    for (int s = 0; s < NSEG; ++s) {
        if (s > 0) __syncthreads();   // prior segment's readers done before overwrite
        // ---- stage A segment s (single buffer) ----
        {
            const __nv_bfloat16* wsrc = wp + (size_t)s * CIN;
            for (int i = tid; i < 128 * GPB; i += NTH) {
                int r = i / GPB, gi = i - r * GPB;
                cp16(smA + r * RB + gi * 16, wsrc + (size_t)r * KTOT + gi * 8, true);
            }
            cp_commit();
        }
        cp_wait0();            // also covers B on s=0
        __syncthreads();

        // segment -> (x buffer, row shift)
        const bool xlo  = (KSIZE == 2) ? (s >= 4) : (s == 1);
        const int  rAdd = (KSIZE == 2) ? ((s & 1) ? D : 0) : 0;

        const uint32_t aBase = (uint32_t)__cvta_generic_to_shared(smA) +
                               aRow * RB + aColB;
        const uint32_t bBase = (uint32_t)__cvta_generic_to_shared(xlo ? smBlo : smBhi) +
                               (bRow + rAdd) * RB + bColB;

        #pragma unroll
        for (int kk = 0; kk < KS; ++kk) {
            const uint32_t ko = kk * 32;   // 16 bf16
            uint32_t a[4][4];
            #pragma unroll
            for (int mt = 0; mt < 4; ++mt)
                ldmx4(a[mt], aBase + mt * 16 * RB + ko);
            uint32_t b0[4], b1[4];
            ldmx4(b0, bBase + ko);                 // n tiles 0,1
            ldmx4(b1, bBase + 16 * RB + ko);       // n tiles 2,3
            #pragma unroll
            for (int mt = 0; mt < 4; ++mt) {
                mma16816(acc[mt][0], a[mt], b0[0], b0[1]);
                mma16816(acc[mt][1], a[mt], b0[2], b0[3]);
                mma16816(acc[mt][2], a[mt], b1[0], b1[1]);
                mma16816(acc[mt][3], a[mt], b1[2], b1[3]);
            }
        }
    }

    __syncthreads();   // compute done; smem reusable

    // ---- phase A: accum -> smem [t][co] (raw, bias added in phase B) ----
    {
        int g = lane >> 2, tig = lane & 3;
        #pragma unroll
        for (int mt = 0; mt < 4; ++mt)
            #pragma unroll
            for (int nt = 0; nt < 4; ++nt)
                #pragma unroll
                for (int j = 0; j < 4; ++j) {
                    int co = m0w + mt * 16 + g + ((j & 2) ? 8 : 0);
                    int tl = n0w + nt * 8 + tig * 2 + (j & 1);
                    tr[tl * TRS + co] = acc[mt][nt][j];
                }
    }
    __syncthreads();

    // ---- phase B: vectorized epilogue, co-pairs, [t][co] order ----
    {
        const int co2 = (tid & 127 & 126);                // even co of this pair
        // remap: thread pairs share work; use tid&63 for pair id, tid>>6 for row set
        const int cp = (tid & 63) * 2;                    // co pair base 0..126
        const int rr = tid >> 6;                          // 0..3
        const float bv0 = __ldg(bias + cp);
        const float bv1 = __ldg(bias + cp + 1);
        (void)co2;
        #pragma unroll 4
        for (int i = 0; i < 32; ++i) {
            int r = rr + 4 * i;
            int t = t0 + r;
            size_t gidx = ((size_t)(b * 4096 + t)) * 128 + cp;
            float2 v = *(float2*)&tr[r * TRS + cp];
            float y0 = v.x + bv0, y1 = v.y + bv1;
            if (MODE == 0) {
                y0 = eluf(y0); y1 = eluf(y1);
            } else if (MODE == 1 || MODE == 2) {
                float r0, r1;
                if (RESF32) {
                    float2 rv = *(const float2*)((const float*)res_h + gidx);
                    r0 = rv.x; r1 = rv.y;
                } else {
                    __nv_bfloat162 rh = *(const __nv_bfloat162*)((const __nv_bfloat16*)res_h + gidx);
                    __nv_bfloat162 rl = *(const __nv_bfloat162*)(res_l + gidx);
                    r0 = __low2float(rh) + __low2float(rl);
                    r1 = __high2float(rh) + __high2float(rl);
                }
                y0 = eluf(eluf(y0) + r0);
                y1 = eluf(eluf(y1) + r1);
                if (MODE == 2) {
                    __nv_bfloat162 sh = *(const __nv_bfloat162*)(skip_h + gidx);
                    __nv_bfloat162 sl = *(const __nv_bfloat162*)(skip_l + gidx);
                    y0 += __low2float(sh) + __low2float(sl);
                    y1 += __high2float(sh) + __high2float(sl);
                }
            }
            if (MODE == 3) {
                *(float2*)((float*)out_h + gidx) = make_float2(y0, y1);
            } else if (MODE == 2) {
                *(float2*)&tr[r * TRS + cp] = make_float2(y0, y1);   // own slot
            } else {
                __nv_bfloat162 hh = __floats2bfloat162_rn(y0, y1);
                *(__nv_bfloat162*)((__nv_bfloat16*)out_h + gidx) = hh;
                float l0 = y0 - __low2float(hh);
                float l1 = y1 - __high2float(hh);
                *(__nv_bfloat162*)(out_l + gidx) = __floats2bfloat162_rn(l0, l1);
            }
        }
    }

    if (MODE == 2) {
        __syncthreads();
        float* outp = (float*)out_h;
        for (int co = w; co < 128; co += 8) {
            #pragma unroll
            for (int m = 0; m < 4; ++m) {
                int r = lane + 32 * m;
                outp[((size_t)(b * 128 + co)) * 4096 + t0 + r] = tr[r * TRS + co];
            }
        }
    }
}

// ============================ scratch ============================

#define AE64  ((size_t)16 * 4096 * 64)
#define AE128 ((size_t)16 * 4096 * 128)
__device__ __nv_bfloat16 g_a0h[AE64], g_a0l[AE64];
__device__ __nv_bfloat16 g_Th[AE128], g_Tl[AE128];
__device__ __nv_bfloat16 g_Ah[AE128], g_Al[AE128];
__device__ __nv_bfloat16 g_Bh[AE128], g_Bl[AE128];
__device__ __nv_bfloat16 g_Ch[AE128], g_Cl[AE128];
__device__ float         g_ds[AE128];
__device__ __nv_bfloat16 g_wp[WP_TOTAL];

// host-side smem size mirror (t-tile = 128, single A buffer, tr stride 130)
static int smem_for(int CIN, int D) {
    int pad = (CIN == 128) ? 136 : 72;
    int rb = pad * 2;
    int stage = (128 + D) * rb * 2 + 128 * rb;
    int tr = 128 * 130 * 4;
    return stage > tr ? stage : tr;
}

// ============================ launcher ============================

extern "C" void kernel_launch(void* const* d_in, const int* in_sizes, int n_in,
                              void* d_out, int out_size) {
    const float* x    = (const float*)d_in[0];
    const float* w1_0 = (const float*)d_in[1];
    const float* b1_0 = (const float*)d_in[2];
    const float* w2_0 = (const float*)d_in[3];
    const float* b2_0 = (const float*)d_in[4];
    const float* ds_w = (const float*)d_in[5];
    const float* ds_b = (const float*)d_in[6];
    const float* W1   = (const float*)d_in[7];
    const float* B1   = (const float*)d_in[8];
    const float* W2   = (const float*)d_in[9];
    const float* B2   = (const float*)d_in[10];
    float* out = (float*)d_out;

    __nv_bfloat16 *a0h, *a0l, *Th, *Tl, *Ah, *Al, *Bh, *Bl, *Ch, *Cl, *wp;
    float *dsO;
    cudaGetSymbolAddress((void**)&a0h, g_a0h); cudaGetSymbolAddress((void**)&a0l, g_a0l);
    cudaGetSymbolAddress((void**)&Th, g_Th);   cudaGetSymbolAddress((void**)&Tl, g_Tl);
    cudaGetSymbolAddress((void**)&Ah, g_Ah);   cudaGetSymbolAddress((void**)&Al, g_Al);
    cudaGetSymbolAddress((void**)&Bh, g_Bh);   cudaGetSymbolAddress((void**)&Bl, g_Bl);
    cudaGetSymbolAddress((void**)&Ch, g_Ch);   cudaGetSymbolAddress((void**)&Cl, g_Cl);
    cudaGetSymbolAddress((void**)&dsO, g_ds);  cudaGetSymbolAddress((void**)&wp, g_wp);

    prep_weights<<<512, 256>>>(ds_w, w1_0, w2_0, W1, W2, wp);
    prep_acts<<<dim3(128, 2, 16), 256>>>(x, a0h, a0l);

    dim3 grid(32, 16);

    #define SETSM(CIN, KS, MODE, D, RF) cudaFuncSetAttribute( \
        (conv_tc<CIN, KS, MODE, D, RF>), \
        cudaFuncAttributeMaxDynamicSharedMemorySize, smem_for(CIN, D))
    SETSM(64, 1, 3, 0, false);
    SETSM(64, 2, 0, 1, false);
    SETSM(128, 2, 1, 1, true);
    SETSM(128, 2, 0, 2, false);
    SETSM(128, 2, 1, 2, false);
    SETSM(128, 2, 0, 4, false);
    SETSM(128, 2, 1, 4, false);
    SETSM(128, 2, 0, 8, false);
    SETSM(128, 2, 1, 8, false);
    SETSM(128, 2, 0, 16, false);
    SETSM(128, 2, 2, 16, false);

    // layer 0
    conv_tc<64, 1, 3, 0, false><<<grid, NTH, smem_for(64, 0)>>>(
        a0h, a0l, wp + WP_DS, ds_b, nullptr, nullptr, nullptr, nullptr, dsO, nullptr);
    conv_tc<64, 2, 0, 1, false><<<grid, NTH, smem_for(64, 1)>>>(
        a0h, a0l, wp + WP_C10, b1_0, nullptr, nullptr, nullptr, nullptr, Th, Tl);
    conv_tc<128, 2, 1, 1, true><<<grid, NTH, smem_for(128, 1)>>>(
        Th, Tl, wp + WP_C20, b2_0, dsO, nullptr, nullptr, nullptr, Ah, Al);   // A = x1
    // layer 1 (d=2)
    conv_tc<128, 2, 0, 2, false><<<grid, NTH, smem_for(128, 2)>>>(
        Ah, Al, wp + WP_L(1), B1 + 0, nullptr, nullptr, nullptr, nullptr, Th, Tl);
    conv_tc<128, 2, 1, 2, false><<<grid, NTH, smem_for(128, 2)>>>(
        Th, Tl, wp + WP_L(2), B2 + 0, Ah, Al, nullptr, nullptr, Bh, Bl);      // B = x2
    // layer 2 (d=4)
    conv_tc<128, 2, 0, 4, false><<<grid, NTH, smem_for(128, 4)>>>(
        Bh, Bl, wp + WP_L(3), B1 + 128, nullptr, nullptr, nullptr, nullptr, Th, Tl);
    conv_tc<128, 2, 1, 4, false><<<grid, NTH, smem_for(128, 4)>>>(
        Th, Tl, wp + WP_L(4), B2 + 128, Bh, Bl, nullptr, nullptr, Ch, Cl);    // C = x3
    // layer 3 (d=8)
    conv_tc<128, 2, 0, 8, false><<<grid, NTH, smem_for(128, 8)>>>(
        Ch, Cl, wp + WP_L(5), B1 + 256, nullptr, nullptr, nullptr, nullptr, Th, Tl);
    conv_tc<128, 2, 1, 8, false><<<grid, NTH, smem_for(128, 8)>>>(
        Th, Tl, wp + WP_L(6), B2 + 256, Ch, Cl, nullptr, nullptr, Bh, Bl);    // B = x4
    // layer 4 (d=16) + final skip (x1 = A)
    conv_tc<128, 2, 0, 16, false><<<grid, NTH, smem_for(128, 16)>>>(
        Bh, Bl, wp + WP_L(7), B1 + 384, nullptr, nullptr, nullptr, nullptr, Th, Tl);
    conv_tc<128, 2, 2, 16, false><<<grid, NTH, smem_for(128, 16)>>>(
        Th, Tl, wp + WP_L(8), B2 + 384, Bh, Bl, Ah, Al, out, nullptr);
}